// round 11
// baseline (speedup 1.0000x reference)
#include <cuda_runtime.h>
#include <cuda_fp16.h>

// Shapes: B=512, T=128, N=128, H=256
#define BB 512
#define TT 128
#define NN 128
#define HH 256

__device__ float g_xW[TT * BB * HH];   // [s][b][h]
__device__ float g_Hs2[TT * HH * BB];  // [s][h][b]
__device__ float g_Q[TT * BB * TT];    // [s][b][t]
__device__ float g_preT[BB * TT * NN]; // [b][t][n]

typedef unsigned long long ull;

__device__ __forceinline__ ull pack2(float x, float y) {
    ull r; asm("mov.b64 %0, {%1, %2};" : "=l"(r) : "f"(x), "f"(y)); return r;
}
__device__ __forceinline__ ull dup2(float x) {
    ull r; asm("mov.b64 %0, {%1, %1};" : "=l"(r) : "f"(x)); return r;
}
__device__ __forceinline__ ull ffma2(ull a, ull b, ull c) {
    ull d; asm("fma.rn.f32x2 %0, %1, %2, %3;" : "=l"(d) : "l"(a), "l"(b), "l"(c)); return d;
}
__device__ __forceinline__ void unpk(ull p, float& x, float& y) {
    asm("mov.b64 {%0, %1}, %2;" : "=f"(x), "=f"(y) : "l"(p));
}
union F4U { float4 v; ull u[2]; };

__device__ __forceinline__ float tanh_fast(float x) {
    float y; asm("tanh.approx.f32 %0, %1;" : "=f"(y) : "f"(x)); return y;
}

// ---------------------------------------------------------------------------
// K_noop: keeps the ncu capture slot (4th launch) on the RNN kernel.
// ---------------------------------------------------------------------------
__global__ void k_noop() {}

// ---------------------------------------------------------------------------
// K_xw3: xW[m][h] = data-row(m) @ Wx + b.  (unchanged)
// ---------------------------------------------------------------------------
__global__ __launch_bounds__(256, 2) void k_xw3(const float* __restrict__ data,
                                                const float* __restrict__ Wx,
                                                const float* __restrict__ bvec) {
    __shared__ float sA[2][16][132];
    __shared__ float sB[2][16][128];
    int m0 = blockIdx.x * 128;
    int h0 = blockIdx.y * 128;
    int tid = threadIdx.x;

    int am = tid >> 1;
    int ak = (tid & 1) * 8;
    int m = m0 + am;
    int s = m >> 9, b = m & 511;
    const float* aptr = data + (size_t)b * (TT * NN) + s * NN + ak;
    int kb = tid >> 5;
    int nb = (tid & 31) * 4;
    const float* bptr = Wx + (size_t)kb * HH + h0 + nb;

    float4 pa0 = *(const float4*)(aptr);
    float4 pa1 = *(const float4*)(aptr + 4);
    float4 pb0 = *(const float4*)(bptr);
    float4 pb1 = *(const float4*)(bptr + 8 * HH);
    {
        float av[8] = {pa0.x, pa0.y, pa0.z, pa0.w, pa1.x, pa1.y, pa1.z, pa1.w};
#pragma unroll
        for (int jj = 0; jj < 8; ++jj) sA[0][ak + jj][am] = av[jj];
        *(float4*)&sB[0][kb][nb] = pb0;
        *(float4*)&sB[0][kb + 8][nb] = pb1;
    }
    __syncthreads();

    int ty = tid >> 4, tx = tid & 15;
    int mr = ty * 8, nr = tx * 8;
    ull acc[8][4] = {};

#pragma unroll 2
    for (int c = 0; c < 8; ++c) {
        if (c + 1 < 8) {
            int k0 = (c + 1) * 16;
            pa0 = *(const float4*)(aptr + k0);
            pa1 = *(const float4*)(aptr + k0 + 4);
            pb0 = *(const float4*)(bptr + (size_t)k0 * HH);
            pb1 = *(const float4*)(bptr + (size_t)(k0 + 8) * HH);
        }
        int buf = c & 1;
#pragma unroll
        for (int k = 0; k < 16; ++k) {
            float4 a0 = *(const float4*)&sA[buf][k][mr];
            float4 a1 = *(const float4*)&sA[buf][k][mr + 4];
            F4U b0u, b1u;
            b0u.v = *(const float4*)&sB[buf][k][nr];
            b1u.v = *(const float4*)&sB[buf][k][nr + 4];
            float av[8] = {a0.x, a0.y, a0.z, a0.w, a1.x, a1.y, a1.z, a1.w};
            ull bp[4] = {b0u.u[0], b0u.u[1], b1u.u[0], b1u.u[1]};
#pragma unroll
            for (int r = 0; r < 8; ++r) {
                ull ad = dup2(av[r]);
#pragma unroll
                for (int p = 0; p < 4; ++p) acc[r][p] = ffma2(ad, bp[p], acc[r][p]);
            }
        }
        if (c + 1 < 8) {
            int nbuf = (c + 1) & 1;
            float av[8] = {pa0.x, pa0.y, pa0.z, pa0.w, pa1.x, pa1.y, pa1.z, pa1.w};
#pragma unroll
            for (int jj = 0; jj < 8; ++jj) sA[nbuf][ak + jj][am] = av[jj];
            *(float4*)&sB[nbuf][kb][nb] = pb0;
            *(float4*)&sB[nbuf][kb + 8][nb] = pb1;
            __syncthreads();
        }
    }

    float bias[8];
#pragma unroll
    for (int cc = 0; cc < 8; ++cc) bias[cc] = __ldg(&bvec[h0 + nr + cc]);
#pragma unroll
    for (int r = 0; r < 8; ++r) {
        float o[8];
        unpk(acc[r][0], o[0], o[1]);
        unpk(acc[r][1], o[2], o[3]);
        unpk(acc[r][2], o[4], o[5]);
        unpk(acc[r][3], o[6], o[7]);
        float* op = g_xW + (size_t)(m0 + mr + r) * HH + h0 + nr;
        float4 o0 = {o[0] + bias[0], o[1] + bias[1], o[2] + bias[2], o[3] + bias[3]};
        float4 o1 = {o[4] + bias[4], o[5] + bias[5], o[6] + bias[6], o[7] + bias[7]};
        *(float4*)&op[0] = o0;
        *(float4*)&op[4] = o1;
    }
}

// ---------------------------------------------------------------------------
// K_pre3: preT[b][t][n]  (unchanged)
// ---------------------------------------------------------------------------
__global__ __launch_bounds__(256, 2) void k_pre3(const float* __restrict__ data,
                                                 const float* __restrict__ W1,
                                                 const float* __restrict__ b1) {
    __shared__ float sA[2][16][128];
    __shared__ float sB[2][16][128];
    int b = blockIdx.x;
    int tid = threadIdx.x;

    int kb = tid >> 5;
    int nb = (tid & 31) * 4;
    const float* aptr = W1 + (size_t)kb * TT + nb;
    const float* bptr = data + (size_t)b * (TT * NN) + (size_t)kb * NN + nb;

    float4 pa0 = *(const float4*)(aptr);
    float4 pa1 = *(const float4*)(aptr + 8 * TT);
    float4 pb0 = *(const float4*)(bptr);
    float4 pb1 = *(const float4*)(bptr + 8 * NN);
    *(float4*)&sA[0][kb][nb] = pa0;
    *(float4*)&sA[0][kb + 8][nb] = pa1;
    *(float4*)&sB[0][kb][nb] = pb0;
    *(float4*)&sB[0][kb + 8][nb] = pb1;
    __syncthreads();

    int ty = tid >> 4, tx = tid & 15;
    int mr = ty * 8, nr = tx * 8;
    ull acc[8][4] = {};

#pragma unroll 2
    for (int c = 0; c < 8; ++c) {
        if (c + 1 < 8) {
            int k0 = (c + 1) * 16;
            pa0 = *(const float4*)(aptr + (size_t)k0 * TT);
            pa1 = *(const float4*)(aptr + (size_t)(k0 + 8) * TT);
            pb0 = *(const float4*)(bptr + (size_t)k0 * NN);
            pb1 = *(const float4*)(bptr + (size_t)(k0 + 8) * NN);
        }
        int buf = c & 1;
#pragma unroll
        for (int k = 0; k < 16; ++k) {
            float4 a0 = *(const float4*)&sA[buf][k][mr];
            float4 a1 = *(const float4*)&sA[buf][k][mr + 4];
            F4U b0u, b1u;
            b0u.v = *(const float4*)&sB[buf][k][nr];
            b1u.v = *(const float4*)&sB[buf][k][nr + 4];
            float av[8] = {a0.x, a0.y, a0.z, a0.w, a1.x, a1.y, a1.z, a1.w};
            ull bp[4] = {b0u.u[0], b0u.u[1], b1u.u[0], b1u.u[1]};
#pragma unroll
            for (int r = 0; r < 8; ++r) {
                ull ad = dup2(av[r]);
#pragma unroll
                for (int p = 0; p < 4; ++p) acc[r][p] = ffma2(ad, bp[p], acc[r][p]);
            }
        }
        if (c + 1 < 8) {
            int nbuf = (c + 1) & 1;
            *(float4*)&sA[nbuf][kb][nb] = pa0;
            *(float4*)&sA[nbuf][kb + 8][nb] = pa1;
            *(float4*)&sB[nbuf][kb][nb] = pb0;
            *(float4*)&sB[nbuf][kb + 8][nb] = pb1;
            __syncthreads();
        }
    }

#pragma unroll
    for (int r = 0; r < 8; ++r) {
        int t = mr + r;
        float bt = __ldg(&b1[t]);
        float o[8];
        unpk(acc[r][0], o[0], o[1]);
        unpk(acc[r][1], o[2], o[3]);
        unpk(acc[r][2], o[4], o[5]);
        unpk(acc[r][3], o[6], o[7]);
        float* op = g_preT + (size_t)b * (TT * NN) + (size_t)t * NN + nr;
        float4 o0 = {o[0] + bt, o[1] + bt, o[2] + bt, o[3] + bt};
        float4 o1 = {o[4] + bt, o[5] + bt, o[6] + bt, o[7] + bt};
        *(float4*)&op[0] = o0;
        *(float4*)&op[4] = o1;
    }
}

// ---------------------------------------------------------------------------
// K_rnn12: SIMD-over-k f32x2 accumulation (unchanged from R10; 419us,
// smem-crossbar-bound per ncu: L1=77%).
// ---------------------------------------------------------------------------
__global__ __launch_bounds__(512, 1) void k_rnn12(const float* __restrict__ h0v,
                                                  const float* __restrict__ Wh) {
    extern __shared__ float sm[];
    float* sWT = sm;              // [2][256][100]
    float* sh = sm + 51200;       // [2][4][260]
    float* sred = sh + 2080;      // [256][4]
    int b0 = blockIdx.x * 4;
    int tid = threadIdx.x;
    int j = tid & 255;
    int kh = tid >> 8;

    for (int idx = tid; idx < 192 * 256; idx += 512) {
        int row = idx >> 8;
        int jj = idx & 255;
        int half = row / 96;
        int kl = row - half * 96;
        sWT[(half * 256 + jj) * 100 + kl] = Wh[(size_t)(half * 128 + kl) * HH + jj];
    }
    ull wr2[16];
    {
        const float* wp = Wh + (size_t)(kh * 128 + 96) * HH + j;
#pragma unroll
        for (int c = 0; c < 16; ++c) {
            float w0 = wp[(size_t)(2 * c) * HH];
            float w1 = wp[(size_t)(2 * c + 1) * HH];
            wr2[c] = pack2(w0, w1);
        }
    }
    if (kh == 0) {
#pragma unroll
        for (int r = 0; r < 4; ++r)
            sh[r * 260 + j] = h0v[(size_t)(b0 + r) * HH + j];
    }
    __syncthreads();

    float nx0 = 0.f, nx1 = 0.f, nx2 = 0.f, nx3 = 0.f;
    if (kh == 0) {
        const float* xw = g_xW + (size_t)b0 * HH + j;
        nx0 = xw[0]; nx1 = xw[HH]; nx2 = xw[2 * HH]; nx3 = xw[3 * HH];
    }

    const float* wrow = sWT + (size_t)(kh * 256 + j) * 100;
    int kbase = kh * 128;

    for (int s = 0; s < TT; ++s) {
        const float* shc = sh + (s & 1) * 1040;
        float* shn = sh + (1 - (s & 1)) * 1040;

        float x0, x1, x2, x3;
        if (kh == 0) {
            x0 = nx0; x1 = nx1; x2 = nx2; x3 = nx3;
            if (s + 1 < TT) {
                const float* xw = g_xW + (size_t)(s + 1) * (BB * HH) + (size_t)b0 * HH + j;
                nx0 = xw[0]; nx1 = xw[HH]; nx2 = xw[2 * HH]; nx3 = xw[3 * HH];
            }
        } else {
            x0 = x1 = x2 = x3 = 0.f;
        }

        ull a0 = 0, a1 = 0, a2 = 0, a3 = 0;
#pragma unroll 6
        for (int q = 0; q < 24; ++q) {
            F4U w4; w4.v = *(const float4*)&wrow[q * 4];
            int k0 = kbase + q * 4;
            F4U hq0, hq1, hq2, hq3;
            hq0.v = *(const float4*)&shc[0 * 260 + k0];
            hq1.v = *(const float4*)&shc[1 * 260 + k0];
            hq2.v = *(const float4*)&shc[2 * 260 + k0];
            hq3.v = *(const float4*)&shc[3 * 260 + k0];
            a0 = ffma2(w4.u[0], hq0.u[0], a0); a0 = ffma2(w4.u[1], hq0.u[1], a0);
            a1 = ffma2(w4.u[0], hq1.u[0], a1); a1 = ffma2(w4.u[1], hq1.u[1], a1);
            a2 = ffma2(w4.u[0], hq2.u[0], a2); a2 = ffma2(w4.u[1], hq2.u[1], a2);
            a3 = ffma2(w4.u[0], hq3.u[0], a3); a3 = ffma2(w4.u[1], hq3.u[1], a3);
        }
#pragma unroll
        for (int q = 0; q < 8; ++q) {
            int k0 = kbase + 96 + q * 4;
            ull w01 = wr2[2 * q], w23 = wr2[2 * q + 1];
            F4U hq0, hq1, hq2, hq3;
            hq0.v = *(const float4*)&shc[0 * 260 + k0];
            hq1.v = *(const float4*)&shc[1 * 260 + k0];
            hq2.v = *(const float4*)&shc[2 * 260 + k0];
            hq3.v = *(const float4*)&shc[3 * 260 + k0];
            a0 = ffma2(w01, hq0.u[0], a0); a0 = ffma2(w23, hq0.u[1], a0);
            a1 = ffma2(w01, hq1.u[0], a1); a1 = ffma2(w23, hq1.u[1], a1);
            a2 = ffma2(w01, hq2.u[0], a2); a2 = ffma2(w23, hq2.u[1], a2);
            a3 = ffma2(w01, hq3.u[0], a3); a3 = ffma2(w23, hq3.u[1], a3);
        }

        float p0, p1, p2, p3;
        { float lo, hi; unpk(a0, lo, hi); p0 = lo + hi; }
        { float lo, hi; unpk(a1, lo, hi); p1 = lo + hi; }
        { float lo, hi; unpk(a2, lo, hi); p2 = lo + hi; }
        { float lo, hi; unpk(a3, lo, hi); p3 = lo + hi; }

        if (kh == 1) {
            *(float4*)&sred[j * 4] = make_float4(p0, p1, p2, p3);
        }
        __syncthreads();
        if (kh == 0) {
            float4 pr = *(const float4*)&sred[j * 4];
            float t0 = tanh_fast(p0 + pr.x + x0);
            float t1 = tanh_fast(p1 + pr.y + x1);
            float t2 = tanh_fast(p2 + pr.z + x2);
            float t3 = tanh_fast(p3 + pr.w + x3);
            shn[0 * 260 + j] = t0;
            shn[1 * 260 + j] = t1;
            shn[2 * 260 + j] = t2;
            shn[3 * 260 + j] = t3;
            *(float4*)&g_Hs2[((size_t)s * HH + j) * BB + b0] = make_float4(t0, t1, t2, t3);
        }
        __syncthreads();
    }
}

// ---------------------------------------------------------------------------
// K_q3: Q[m][t] = Hs-row(m) @ W2 + b2. (unchanged)
// ---------------------------------------------------------------------------
__global__ __launch_bounds__(256, 2) void k_q3(const float* __restrict__ W2,
                                               const float* __restrict__ b2) {
    __shared__ float sA[2][16][132];
    __shared__ float sB[2][16][128];
    int m0 = blockIdx.x * 128;
    int s = m0 >> 9, b0m = m0 & 511;
    int tid = threadIdx.x;

    int kk0 = tid >> 5;
    int mmo = (tid & 31) * 4;
    int kk1 = kk0 + 8;
    const float* aB = g_Hs2 + (size_t)s * HH * BB + b0m + mmo;
    int kb = tid >> 5;
    int nb = (tid & 31) * 4;
    const float* bptr = W2 + (size_t)kb * TT + nb;

    float4 pa0 = *(const float4*)&aB[(size_t)kk0 * BB];
    float4 pa1 = *(const float4*)&aB[(size_t)kk1 * BB];
    float4 pb0 = *(const float4*)(bptr);
    float4 pb1 = *(const float4*)(bptr + 8 * TT);
    *(float4*)&sA[0][kk0][mmo] = pa0;
    *(float4*)&sA[0][kk1][mmo] = pa1;
    *(float4*)&sB[0][kb][nb] = pb0;
    *(float4*)&sB[0][kb + 8][nb] = pb1;
    __syncthreads();

    int ty = tid >> 4, tx = tid & 15;
    int mr = ty * 8, nr = tx * 8;
    ull acc[8][4] = {};

#pragma unroll 2
    for (int c = 0; c < 16; ++c) {
        if (c + 1 < 16) {
            int k0 = (c + 1) * 16;
            pa0 = *(const float4*)&aB[(size_t)(k0 + kk0) * BB];
            pa1 = *(const float4*)&aB[(size_t)(k0 + kk1) * BB];
            pb0 = *(const float4*)(bptr + (size_t)k0 * TT);
            pb1 = *(const float4*)(bptr + (size_t)(k0 + 8) * TT);
        }
        int buf = c & 1;
#pragma unroll
        for (int k = 0; k < 16; ++k) {
            float4 a0 = *(const float4*)&sA[buf][k][mr];
            float4 a1 = *(const float4*)&sA[buf][k][mr + 4];
            F4U b0u, b1u;
            b0u.v = *(const float4*)&sB[buf][k][nr];
            b1u.v = *(const float4*)&sB[buf][k][nr + 4];
            float av[8] = {a0.x, a0.y, a0.z, a0.w, a1.x, a1.y, a1.z, a1.w};
            ull bp[4] = {b0u.u[0], b0u.u[1], b1u.u[0], b1u.u[1]};
#pragma unroll
            for (int r = 0; r < 8; ++r) {
                ull ad = dup2(av[r]);
#pragma unroll
                for (int p = 0; p < 4; ++p) acc[r][p] = ffma2(ad, bp[p], acc[r][p]);
            }
        }
        if (c + 1 < 16) {
            int nbuf = (c + 1) & 1;
            *(float4*)&sA[nbuf][kk0][mmo] = pa0;
            *(float4*)&sA[nbuf][kk1][mmo] = pa1;
            *(float4*)&sB[nbuf][kb][nb] = pb0;
            *(float4*)&sB[nbuf][kb + 8][nb] = pb1;
            __syncthreads();
        }
    }

    float bias[8];
#pragma unroll
    for (int cc = 0; cc < 8; ++cc) bias[cc] = __ldg(&b2[nr + cc]);
#pragma unroll
    for (int r = 0; r < 8; ++r) {
        float o[8];
        unpk(acc[r][0], o[0], o[1]);
        unpk(acc[r][1], o[2], o[3]);
        unpk(acc[r][2], o[4], o[5]);
        unpk(acc[r][3], o[6], o[7]);
        float* op = g_Q + (size_t)(m0 + mr + r) * TT + nr;
        float4 o0 = {o[0] + bias[0], o[1] + bias[1], o[2] + bias[2], o[3] + bias[3]};
        float4 o1 = {o[4] + bias[4], o[5] + bias[5], o[6] + bias[6], o[7] + bias[7]};
        *(float4*)&op[0] = o0;
        *(float4*)&op[4] = o1;
    }
}

// ---------------------------------------------------------------------------
// K_att4: scores via tanh.approx.f16x2 (2 tanh per MUFU op — halves the
// binding MUFU pipe). Pack two fp32 pre-activations -> f16x2, MUFU tanh,
// unpack to fp32, accumulate in fp32. Softmax + fused output mul unchanged.
// ---------------------------------------------------------------------------
__global__ __launch_bounds__(256) void k_att4(const float* __restrict__ data,
                                              const float* __restrict__ Wv,
                                              float* __restrict__ out) {
    extern __shared__ float sm[];
    float* sP = sm;
    float* sQ = sm + 16384;
    float* sWv = sQ + 256;
    float* sred = sWv + 128;
    int b = blockIdx.x >> 1;
    int shalf = blockIdx.x & 1;
    int tid = threadIdx.x;

    const float4* gP = (const float4*)(g_preT + (size_t)b * (TT * NN));
    for (int i = tid; i < 4096; i += 256) ((float4*)sP)[i] = gP[i];
    if (tid < 128) sWv[tid] = Wv[tid];
    __syncthreads();

    int n = tid & 127;
    int grp = tid >> 7;
    int lane = tid & 31;
    int wig = (tid >> 5) & 3;

    for (int si = 0; si < 32; ++si) {
        int s = shalf * 64 + si * 2 + grp;
        sQ[tid] = g_Q[(size_t)s * (BB * TT) + b * TT + n];
        __syncthreads();

        const float* qrow = sQ + grp * 128;
        float e = 0.f;
#pragma unroll 4
        for (int t = 0; t < 128; t += 2) {
            float s0 = sP[t * 128 + n] + qrow[t];
            float s1 = sP[(t + 1) * 128 + n] + qrow[t + 1];
            unsigned int hp;
            asm("cvt.rn.f16x2.f32 %0, %1, %2;" : "=r"(hp) : "f"(s1), "f"(s0));  // hi=s1, lo=s0
            asm("tanh.approx.f16x2 %0, %0;" : "+r"(hp));
            __half2 th = *reinterpret_cast<__half2*>(&hp);
            float2 tf = __half22float2(th);   // .x = lo (t), .y = hi (t+1)
            e += sWv[t] * tf.x + sWv[t + 1] * tf.y;
        }

        float ex = __expf(e);
        float sum = ex;
#pragma unroll
        for (int o = 16; o; o >>= 1) sum += __shfl_xor_sync(0xFFFFFFFFu, sum, o);
        if (lane == 0) sred[grp * 4 + wig] = sum;
        __syncthreads();
        sum = sred[grp * 4 + 0] + sred[grp * 4 + 1] + sred[grp * 4 + 2] + sred[grp * 4 + 3];
        float alpha = ex / sum;

        int bp = 4 * s + (b >> 7);
        int tp = b & 127;
        size_t idx = (size_t)bp * (TT * NN) + tp * NN + n;
        out[idx] = data[idx] * alpha;
        __syncthreads();
    }
}

// ---------------------------------------------------------------------------
extern "C" void kernel_launch(void* const* d_in, const int* in_sizes, int n_in,
                              void* d_out, int out_size) {
    const float* data = (const float*)d_in[0];
    const float* h0 = (const float*)d_in[1];
    const float* Wx = (const float*)d_in[2];
    const float* Wh = (const float*)d_in[3];
    const float* bvec = (const float*)d_in[4];
    const float* W1 = (const float*)d_in[5];
    const float* b1 = (const float*)d_in[6];
    const float* W2 = (const float*)d_in[7];
    const float* b2 = (const float*)d_in[8];
    const float* Wv = (const float*)d_in[9];
    float* out = (float*)d_out;

    const int SM_RNN = (51200 + 2080 + 1024) * 4;        // 217,216 B
    const int SM_ATT = (128 * 128 + 256 + 128 + 8) * 4;  // ~66 KB

    cudaFuncSetAttribute(k_rnn12, cudaFuncAttributeMaxDynamicSharedMemorySize, SM_RNN);
    cudaFuncSetAttribute(k_att4, cudaFuncAttributeMaxDynamicSharedMemorySize, SM_ATT);

    k_noop<<<1, 1>>>();  // keeps ncu capture (4th launch) on k_rnn12
    k_xw3<<<dim3((TT * BB) / 128, HH / 128), 256>>>(data, Wx, bvec);
    k_pre3<<<BB, 256>>>(data, W1, b1);
    k_rnn12<<<BB / 4, 512, SM_RNN>>>(h0, Wh);
    k_q3<<<(TT * BB) / 128, 256>>>(W2, b2);
    k_att4<<<BB * 2, 256, SM_ATT>>>(data, Wv, out);
}

// round 12
// speedup vs baseline: 1.1160x; 1.1160x over previous
#include <cuda_runtime.h>

// Shapes: B=512, T=128, N=128, H=256
#define BB 512
#define TT 128
#define NN 128
#define HH 256

__device__ float g_xW[TT * BB * HH];   // [s][b][h]
__device__ float g_Hs2[TT * HH * BB];  // [s][h][b]
__device__ float g_Q[TT * BB * TT];    // [s][b][t]
__device__ float g_preT[BB * TT * NN]; // [b][t][n]

typedef unsigned long long ull;

__device__ __forceinline__ ull pack2(float x, float y) {
    ull r; asm("mov.b64 %0, {%1, %2};" : "=l"(r) : "f"(x), "f"(y)); return r;
}
__device__ __forceinline__ ull dup2(float x) {
    ull r; asm("mov.b64 %0, {%1, %1};" : "=l"(r) : "f"(x)); return r;
}
__device__ __forceinline__ ull ffma2(ull a, ull b, ull c) {
    ull d; asm("fma.rn.f32x2 %0, %1, %2, %3;" : "=l"(d) : "l"(a), "l"(b), "l"(c)); return d;
}
__device__ __forceinline__ ull fadd2(ull a, ull b) {
    ull d; asm("add.rn.f32x2 %0, %1, %2;" : "=l"(d) : "l"(a), "l"(b)); return d;
}
__device__ __forceinline__ void unpk(ull p, float& x, float& y) {
    asm("mov.b64 {%0, %1}, %2;" : "=f"(x), "=f"(y) : "l"(p));
}
union F4U { float4 v; ull u[2]; };

__device__ __forceinline__ float tanh_fast(float x) {
    float y; asm("tanh.approx.f32 %0, %1;" : "=f"(y) : "f"(x)); return y;
}

// ---------------------------------------------------------------------------
// K_noop: keeps the ncu capture slot (4th launch) on the RNN kernel.
// ---------------------------------------------------------------------------
__global__ void k_noop() {}

// ---------------------------------------------------------------------------
// K_xw3: xW[m][h] = data-row(m) @ Wx + b.  (unchanged)
// ---------------------------------------------------------------------------
__global__ __launch_bounds__(256, 2) void k_xw3(const float* __restrict__ data,
                                                const float* __restrict__ Wx,
                                                const float* __restrict__ bvec) {
    __shared__ float sA[2][16][132];
    __shared__ float sB[2][16][128];
    int m0 = blockIdx.x * 128;
    int h0 = blockIdx.y * 128;
    int tid = threadIdx.x;

    int am = tid >> 1;
    int ak = (tid & 1) * 8;
    int m = m0 + am;
    int s = m >> 9, b = m & 511;
    const float* aptr = data + (size_t)b * (TT * NN) + s * NN + ak;
    int kb = tid >> 5;
    int nb = (tid & 31) * 4;
    const float* bptr = Wx + (size_t)kb * HH + h0 + nb;

    float4 pa0 = *(const float4*)(aptr);
    float4 pa1 = *(const float4*)(aptr + 4);
    float4 pb0 = *(const float4*)(bptr);
    float4 pb1 = *(const float4*)(bptr + 8 * HH);
    {
        float av[8] = {pa0.x, pa0.y, pa0.z, pa0.w, pa1.x, pa1.y, pa1.z, pa1.w};
#pragma unroll
        for (int jj = 0; jj < 8; ++jj) sA[0][ak + jj][am] = av[jj];
        *(float4*)&sB[0][kb][nb] = pb0;
        *(float4*)&sB[0][kb + 8][nb] = pb1;
    }
    __syncthreads();

    int ty = tid >> 4, tx = tid & 15;
    int mr = ty * 8, nr = tx * 8;
    ull acc[8][4] = {};

#pragma unroll 2
    for (int c = 0; c < 8; ++c) {
        if (c + 1 < 8) {
            int k0 = (c + 1) * 16;
            pa0 = *(const float4*)(aptr + k0);
            pa1 = *(const float4*)(aptr + k0 + 4);
            pb0 = *(const float4*)(bptr + (size_t)k0 * HH);
            pb1 = *(const float4*)(bptr + (size_t)(k0 + 8) * HH);
        }
        int buf = c & 1;
#pragma unroll
        for (int k = 0; k < 16; ++k) {
            float4 a0 = *(const float4*)&sA[buf][k][mr];
            float4 a1 = *(const float4*)&sA[buf][k][mr + 4];
            F4U b0u, b1u;
            b0u.v = *(const float4*)&sB[buf][k][nr];
            b1u.v = *(const float4*)&sB[buf][k][nr + 4];
            float av[8] = {a0.x, a0.y, a0.z, a0.w, a1.x, a1.y, a1.z, a1.w};
            ull bp[4] = {b0u.u[0], b0u.u[1], b1u.u[0], b1u.u[1]};
#pragma unroll
            for (int r = 0; r < 8; ++r) {
                ull ad = dup2(av[r]);
#pragma unroll
                for (int p = 0; p < 4; ++p) acc[r][p] = ffma2(ad, bp[p], acc[r][p]);
            }
        }
        if (c + 1 < 8) {
            int nbuf = (c + 1) & 1;
            float av[8] = {pa0.x, pa0.y, pa0.z, pa0.w, pa1.x, pa1.y, pa1.z, pa1.w};
#pragma unroll
            for (int jj = 0; jj < 8; ++jj) sA[nbuf][ak + jj][am] = av[jj];
            *(float4*)&sB[nbuf][kb][nb] = pb0;
            *(float4*)&sB[nbuf][kb + 8][nb] = pb1;
            __syncthreads();
        }
    }

    float bias[8];
#pragma unroll
    for (int cc = 0; cc < 8; ++cc) bias[cc] = __ldg(&bvec[h0 + nr + cc]);
#pragma unroll
    for (int r = 0; r < 8; ++r) {
        float o[8];
        unpk(acc[r][0], o[0], o[1]);
        unpk(acc[r][1], o[2], o[3]);
        unpk(acc[r][2], o[4], o[5]);
        unpk(acc[r][3], o[6], o[7]);
        float* op = g_xW + (size_t)(m0 + mr + r) * HH + h0 + nr;
        float4 o0 = {o[0] + bias[0], o[1] + bias[1], o[2] + bias[2], o[3] + bias[3]};
        float4 o1 = {o[4] + bias[4], o[5] + bias[5], o[6] + bias[6], o[7] + bias[7]};
        *(float4*)&op[0] = o0;
        *(float4*)&op[4] = o1;
    }
}

// ---------------------------------------------------------------------------
// K_pre3: preT[b][t][n]  (unchanged)
// ---------------------------------------------------------------------------
__global__ __launch_bounds__(256, 2) void k_pre3(const float* __restrict__ data,
                                                 const float* __restrict__ W1,
                                                 const float* __restrict__ b1) {
    __shared__ float sA[2][16][128];
    __shared__ float sB[2][16][128];
    int b = blockIdx.x;
    int tid = threadIdx.x;

    int kb = tid >> 5;
    int nb = (tid & 31) * 4;
    const float* aptr = W1 + (size_t)kb * TT + nb;
    const float* bptr = data + (size_t)b * (TT * NN) + (size_t)kb * NN + nb;

    float4 pa0 = *(const float4*)(aptr);
    float4 pa1 = *(const float4*)(aptr + 8 * TT);
    float4 pb0 = *(const float4*)(bptr);
    float4 pb1 = *(const float4*)(bptr + 8 * NN);
    *(float4*)&sA[0][kb][nb] = pa0;
    *(float4*)&sA[0][kb + 8][nb] = pa1;
    *(float4*)&sB[0][kb][nb] = pb0;
    *(float4*)&sB[0][kb + 8][nb] = pb1;
    __syncthreads();

    int ty = tid >> 4, tx = tid & 15;
    int mr = ty * 8, nr = tx * 8;
    ull acc[8][4] = {};

#pragma unroll 2
    for (int c = 0; c < 8; ++c) {
        if (c + 1 < 8) {
            int k0 = (c + 1) * 16;
            pa0 = *(const float4*)(aptr + (size_t)k0 * TT);
            pa1 = *(const float4*)(aptr + (size_t)(k0 + 8) * TT);
            pb0 = *(const float4*)(bptr + (size_t)k0 * NN);
            pb1 = *(const float4*)(bptr + (size_t)(k0 + 8) * NN);
        }
        int buf = c & 1;
#pragma unroll
        for (int k = 0; k < 16; ++k) {
            float4 a0 = *(const float4*)&sA[buf][k][mr];
            float4 a1 = *(const float4*)&sA[buf][k][mr + 4];
            F4U b0u, b1u;
            b0u.v = *(const float4*)&sB[buf][k][nr];
            b1u.v = *(const float4*)&sB[buf][k][nr + 4];
            float av[8] = {a0.x, a0.y, a0.z, a0.w, a1.x, a1.y, a1.z, a1.w};
            ull bp[4] = {b0u.u[0], b0u.u[1], b1u.u[0], b1u.u[1]};
#pragma unroll
            for (int r = 0; r < 8; ++r) {
                ull ad = dup2(av[r]);
#pragma unroll
                for (int p = 0; p < 4; ++p) acc[r][p] = ffma2(ad, bp[p], acc[r][p]);
            }
        }
        if (c + 1 < 8) {
            int nbuf = (c + 1) & 1;
            *(float4*)&sA[nbuf][kb][nb] = pa0;
            *(float4*)&sA[nbuf][kb + 8][nb] = pa1;
            *(float4*)&sB[nbuf][kb][nb] = pb0;
            *(float4*)&sB[nbuf][kb + 8][nb] = pb1;
            __syncthreads();
        }
    }

#pragma unroll
    for (int r = 0; r < 8; ++r) {
        int t = mr + r;
        float bt = __ldg(&b1[t]);
        float o[8];
        unpk(acc[r][0], o[0], o[1]);
        unpk(acc[r][1], o[2], o[3]);
        unpk(acc[r][2], o[4], o[5]);
        unpk(acc[r][3], o[6], o[7]);
        float* op = g_preT + (size_t)b * (TT * NN) + (size_t)t * NN + nr;
        float4 o0 = {o[0] + bt, o[1] + bt, o[2] + bt, o[3] + bt};
        float4 o1 = {o[4] + bt, o[5] + bt, o[6] + bt, o[7] + bt};
        *(float4*)&op[0] = o0;
        *(float4*)&op[4] = o1;
    }
}

// ---------------------------------------------------------------------------
// K_rnn9: best measured RNN (381us in R8 config). 64k smem + 64k regs per
// kh-half, f32x2 packed row-pair accumulators, MUFU tanh, 2 barriers/step.
// ---------------------------------------------------------------------------
__global__ __launch_bounds__(512, 1) void k_rnn9(const float* __restrict__ h0,
                                                 const float* __restrict__ Wh) {
    extern __shared__ float sm[];
    float* sWs = sm;            // [128][256]
    float* sh = sm + 32768;     // [2][256][4]
    float* sred = sh + 2048;    // [256][4]
    int b0 = blockIdx.x * 4;
    int tid = threadIdx.x;
    int j = tid & 255;
    int kh = tid >> 8;

    for (int i = tid; i < 128 * 64; i += 512) {
        int row = i >> 6;
        int c4 = i & 63;
        int gr = (row < 64) ? row : (row + 64);
        ((float4*)sWs)[i] = *(const float4*)&Wh[(size_t)gr * HH + c4 * 4];
    }
    float wr[64];
    {
        const float* wp = Wh + (size_t)(kh * 128 + 64) * HH + j;
#pragma unroll
        for (int c = 0; c < 64; ++c) wr[c] = wp[(size_t)c * HH];
    }
    if (kh == 0) {
        float4 h4;
        h4.x = h0[(size_t)(b0 + 0) * HH + j];
        h4.y = h0[(size_t)(b0 + 1) * HH + j];
        h4.z = h0[(size_t)(b0 + 2) * HH + j];
        h4.w = h0[(size_t)(b0 + 3) * HH + j];
        *(float4*)&sh[j * 4] = h4;
    }
    __syncthreads();

    ull nx01 = 0, nx23 = 0;
    if (kh == 0) {
        const float* xw = g_xW + (size_t)b0 * HH + j;
        nx01 = pack2(xw[0], xw[HH]);
        nx23 = pack2(xw[2 * HH], xw[3 * HH]);
    }

    const float* swj = sWs + j;
    int smbase = kh * 64;
    int hsm = kh * 128;
    int hrg = kh * 128 + 64;

    for (int s = 0; s < TT; ++s) {
        const float* shc = sh + (s & 1) * 1024;
        float* shn = sh + (1 - (s & 1)) * 1024;

        ull a01, a23;
        if (kh == 0) {
            a01 = nx01; a23 = nx23;
            if (s + 1 < TT) {
                const float* xw = g_xW + (size_t)(s + 1) * (BB * HH) + (size_t)b0 * HH + j;
                nx01 = pack2(xw[0], xw[HH]);
                nx23 = pack2(xw[2 * HH], xw[3 * HH]);
            }
        } else {
            a01 = 0; a23 = 0;
        }
        ull c01 = 0, c23 = 0;

#pragma unroll 16
        for (int k = 0; k < 64; ++k) {
            float w = swj[(smbase + k) * 256];
            F4U hu; hu.v = *(const float4*)&shc[(hsm + k) * 4];
            ull wd = dup2(w);
            a01 = ffma2(hu.u[0], wd, a01);
            a23 = ffma2(hu.u[1], wd, a23);
        }
#pragma unroll
        for (int c = 0; c < 64; ++c) {
            ull wd = dup2(wr[c]);
            F4U hu; hu.v = *(const float4*)&shc[(hrg + c) * 4];
            c01 = ffma2(hu.u[0], wd, c01);
            c23 = ffma2(hu.u[1], wd, c23);
        }

        if (kh == 1) {
            F4U r;
            r.u[0] = fadd2(a01, c01);
            r.u[1] = fadd2(a23, c23);
            *(float4*)&sred[j * 4] = r.v;
        }
        __syncthreads();
        if (kh == 0) {
            F4U p; p.v = *(const float4*)&sred[j * 4];
            a01 = fadd2(fadd2(a01, c01), p.u[0]);
            a23 = fadd2(fadd2(a23, c23), p.u[1]);
            float x0, x1, x2, x3;
            unpk(a01, x0, x1);
            unpk(a23, x2, x3);
            float4 h4o = make_float4(tanh_fast(x0), tanh_fast(x1), tanh_fast(x2), tanh_fast(x3));
            *(float4*)&shn[j * 4] = h4o;
            *(float4*)&g_Hs2[((size_t)s * HH + j) * BB + b0] = h4o;
        }
        __syncthreads();
    }
}

// ---------------------------------------------------------------------------
// K_q3: Q[m][t] = Hs-row(m) @ W2 + b2. (unchanged)
// ---------------------------------------------------------------------------
__global__ __launch_bounds__(256, 2) void k_q3(const float* __restrict__ W2,
                                               const float* __restrict__ b2) {
    __shared__ float sA[2][16][132];
    __shared__ float sB[2][16][128];
    int m0 = blockIdx.x * 128;
    int s = m0 >> 9, b0m = m0 & 511;
    int tid = threadIdx.x;

    int kk0 = tid >> 5;
    int mmo = (tid & 31) * 4;
    int kk1 = kk0 + 8;
    const float* aB = g_Hs2 + (size_t)s * HH * BB + b0m + mmo;
    int kb = tid >> 5;
    int nb = (tid & 31) * 4;
    const float* bptr = W2 + (size_t)kb * TT + nb;

    float4 pa0 = *(const float4*)&aB[(size_t)kk0 * BB];
    float4 pa1 = *(const float4*)&aB[(size_t)kk1 * BB];
    float4 pb0 = *(const float4*)(bptr);
    float4 pb1 = *(const float4*)(bptr + 8 * TT);
    *(float4*)&sA[0][kk0][mmo] = pa0;
    *(float4*)&sA[0][kk1][mmo] = pa1;
    *(float4*)&sB[0][kb][nb] = pb0;
    *(float4*)&sB[0][kb + 8][nb] = pb1;
    __syncthreads();

    int ty = tid >> 4, tx = tid & 15;
    int mr = ty * 8, nr = tx * 8;
    ull acc[8][4] = {};

#pragma unroll 2
    for (int c = 0; c < 16; ++c) {
        if (c + 1 < 16) {
            int k0 = (c + 1) * 16;
            pa0 = *(const float4*)&aB[(size_t)(k0 + kk0) * BB];
            pa1 = *(const float4*)&aB[(size_t)(k0 + kk1) * BB];
            pb0 = *(const float4*)(bptr + (size_t)k0 * TT);
            pb1 = *(const float4*)(bptr + (size_t)(k0 + 8) * TT);
        }
        int buf = c & 1;
#pragma unroll
        for (int k = 0; k < 16; ++k) {
            float4 a0 = *(const float4*)&sA[buf][k][mr];
            float4 a1 = *(const float4*)&sA[buf][k][mr + 4];
            F4U b0u, b1u;
            b0u.v = *(const float4*)&sB[buf][k][nr];
            b1u.v = *(const float4*)&sB[buf][k][nr + 4];
            float av[8] = {a0.x, a0.y, a0.z, a0.w, a1.x, a1.y, a1.z, a1.w};
            ull bp[4] = {b0u.u[0], b0u.u[1], b1u.u[0], b1u.u[1]};
#pragma unroll
            for (int r = 0; r < 8; ++r) {
                ull ad = dup2(av[r]);
#pragma unroll
                for (int p = 0; p < 4; ++p) acc[r][p] = ffma2(ad, bp[p], acc[r][p]);
            }
        }
        if (c + 1 < 16) {
            int nbuf = (c + 1) & 1;
            *(float4*)&sA[nbuf][kk0][mmo] = pa0;
            *(float4*)&sA[nbuf][kk1][mmo] = pa1;
            *(float4*)&sB[nbuf][kb][nb] = pb0;
            *(float4*)&sB[nbuf][kb + 8][nb] = pb1;
            __syncthreads();
        }
    }

    float bias[8];
#pragma unroll
    for (int cc = 0; cc < 8; ++cc) bias[cc] = __ldg(&b2[nr + cc]);
#pragma unroll
    for (int r = 0; r < 8; ++r) {
        float o[8];
        unpk(acc[r][0], o[0], o[1]);
        unpk(acc[r][1], o[2], o[3]);
        unpk(acc[r][2], o[4], o[5]);
        unpk(acc[r][3], o[6], o[7]);
        float* op = g_Q + (size_t)(m0 + mr + r) * TT + nr;
        float4 o0 = {o[0] + bias[0], o[1] + bias[1], o[2] + bias[2], o[3] + bias[3]};
        float4 o1 = {o[4] + bias[4], o[5] + bias[5], o[6] + bias[6], o[7] + bias[7]};
        *(float4*)&op[0] = o0;
        *(float4*)&op[4] = o1;
    }
}

// ---------------------------------------------------------------------------
// K_att5: f32 MUFU tanh (att4's f16x2 reverted — it regressed). ONE barrier
// per s-iteration via double-buffered sQ and sred; next-q prefetched before
// the tanh loop; dual e-accumulators.
// ---------------------------------------------------------------------------
__global__ __launch_bounds__(256) void k_att5(const float* __restrict__ data,
                                              const float* __restrict__ Wv,
                                              float* __restrict__ out) {
    extern __shared__ float sm[];
    float* sP = sm;            // [128][128]
    float* sQ = sm + 16384;    // [2][256]
    float* sWv = sQ + 512;     // [128]
    float* sred = sWv + 128;   // [2][8]
    int b = blockIdx.x >> 1;
    int shalf = blockIdx.x & 1;
    int tid = threadIdx.x;

    const float4* gP = (const float4*)(g_preT + (size_t)b * (TT * NN));
    for (int i = tid; i < 4096; i += 256) ((float4*)sP)[i] = gP[i];
    if (tid < 128) sWv[tid] = Wv[tid];

    int n = tid & 127;
    int grp = tid >> 7;
    int lane = tid & 31;
    int wig = (tid >> 5) & 3;

    // preload first q into buffer 0
    sQ[tid] = g_Q[(size_t)(shalf * 64 + grp) * (BB * TT) + b * TT + n];
    __syncthreads();

    for (int si = 0; si < 32; ++si) {
        int cur = si & 1;
        int s = shalf * 64 + si * 2 + grp;

        // prefetch next q (LDG issued before the long tanh loop)
        float qn = 0.f;
        if (si + 1 < 32) {
            qn = g_Q[(size_t)(s + 2) * (BB * TT) + b * TT + n];
        }

        const float* qrow = sQ + cur * 256 + grp * 128;
        float e0 = 0.f, e1 = 0.f;
#pragma unroll 4
        for (int t = 0; t < 128; t += 2) {
            e0 += sWv[t] * tanh_fast(sP[t * 128 + n] + qrow[t]);
            e1 += sWv[t + 1] * tanh_fast(sP[(t + 1) * 128 + n] + qrow[t + 1]);
        }
        float e = e0 + e1;

        float ex = __expf(e);
        float sum = ex;
#pragma unroll
        for (int o = 16; o; o >>= 1) sum += __shfl_xor_sync(0xFFFFFFFFu, sum, o);
        if (lane == 0) sred[cur * 8 + grp * 4 + wig] = sum;
        if (si + 1 < 32) sQ[(cur ^ 1) * 256 + tid] = qn;
        __syncthreads();  // single barrier per iteration

        const float* sr = sred + cur * 8 + grp * 4;
        sum = sr[0] + sr[1] + sr[2] + sr[3];
        float alpha = ex / sum;

        int bp = 4 * s + (b >> 7);
        int tp = b & 127;
        size_t idx = (size_t)bp * (TT * NN) + tp * NN + n;
        out[idx] = data[idx] * alpha;
    }
}

// ---------------------------------------------------------------------------
extern "C" void kernel_launch(void* const* d_in, const int* in_sizes, int n_in,
                              void* d_out, int out_size) {
    const float* data = (const float*)d_in[0];
    const float* h0 = (const float*)d_in[1];
    const float* Wx = (const float*)d_in[2];
    const float* Wh = (const float*)d_in[3];
    const float* bvec = (const float*)d_in[4];
    const float* W1 = (const float*)d_in[5];
    const float* b1 = (const float*)d_in[6];
    const float* W2 = (const float*)d_in[7];
    const float* b2 = (const float*)d_in[8];
    const float* Wv = (const float*)d_in[9];
    float* out = (float*)d_out;

    const int SM_RNN = (32768 + 2048 + 1024) * 4;            // 140 KB
    const int SM_ATT = (16384 + 512 + 128 + 16) * 4;         // ~68 KB

    cudaFuncSetAttribute(k_rnn9, cudaFuncAttributeMaxDynamicSharedMemorySize, SM_RNN);
    cudaFuncSetAttribute(k_att5, cudaFuncAttributeMaxDynamicSharedMemorySize, SM_ATT);

    k_noop<<<1, 1>>>();  // keeps ncu capture (4th launch) on k_rnn9
    k_xw3<<<dim3((TT * BB) / 128, HH / 128), 256>>>(data, Wx, bvec);
    k_pre3<<<BB, 256>>>(data, W1, b1);
    k_rnn9<<<BB / 4, 512, SM_RNN>>>(h0, Wh);
    k_q3<<<(TT * BB) / 128, 256>>>(W2, b2);
    k_att5<<<BB * 2, 256, SM_ATT>>>(data, Wv, out);
}

// round 13
// speedup vs baseline: 1.1374x; 1.0191x over previous
#include <cuda_runtime.h>

// Shapes: B=512, T=128, N=128, H=256
#define BB 512
#define TT 128
#define NN 128
#define HH 256

__device__ float g_xW[TT * BB * HH];   // [s][b][h]
__device__ float g_Hs2[TT * HH * BB];  // [s][h][b]
__device__ float g_Q[TT * BB * TT];    // [s][b][t]
__device__ float g_preT[BB * TT * NN]; // [b][t][n]

typedef unsigned long long ull;

__device__ __forceinline__ ull pack2(float x, float y) {
    ull r; asm("mov.b64 %0, {%1, %2};" : "=l"(r) : "f"(x), "f"(y)); return r;
}
__device__ __forceinline__ ull dup2(float x) {
    ull r; asm("mov.b64 %0, {%1, %1};" : "=l"(r) : "f"(x)); return r;
}
__device__ __forceinline__ ull ffma2(ull a, ull b, ull c) {
    ull d; asm("fma.rn.f32x2 %0, %1, %2, %3;" : "=l"(d) : "l"(a), "l"(b), "l"(c)); return d;
}
__device__ __forceinline__ ull fadd2(ull a, ull b) {
    ull d; asm("add.rn.f32x2 %0, %1, %2;" : "=l"(d) : "l"(a), "l"(b)); return d;
}
__device__ __forceinline__ void unpk(ull p, float& x, float& y) {
    asm("mov.b64 {%0, %1}, %2;" : "=f"(x), "=f"(y) : "l"(p));
}
union F4U { float4 v; ull u[2]; };

__device__ __forceinline__ float tanh_fast(float x) {
    float y; asm("tanh.approx.f32 %0, %1;" : "=f"(y) : "f"(x)); return y;
}

// ---------------------------------------------------------------------------
// K_xwpre: merged k_xw3 + k_pre3 (independent GEMMs, concurrent residency).
// Blocks [0,1024): xW[m][h] = data-row(m) @ Wx + bvec   (m0, h0 tiling)
// Blocks [1024,1536): preT[b][t][n] = sum_tau W1[tau][t]*data[b][tau][n]+b1[t]
// One 33,280-byte shared buffer reused by both paths.
// ---------------------------------------------------------------------------
__global__ __launch_bounds__(256, 2) void k_xwpre(const float* __restrict__ data,
                                                  const float* __restrict__ Wx,
                                                  const float* __restrict__ bvec,
                                                  const float* __restrict__ W1,
                                                  const float* __restrict__ b1) {
    __shared__ __align__(16) unsigned char smbuf[33280];
    int tid = threadIdx.x;

    if (blockIdx.x < 1024) {
        // ------------------- xW path -------------------
        float* sA = (float*)smbuf;               // [2][16][132]
        float* sB = (float*)(smbuf + 16896);     // [2][16][128]
        int m0 = (blockIdx.x & 511) * 128;
        int h0 = (blockIdx.x >> 9) * 128;

        int am = tid >> 1;
        int ak = (tid & 1) * 8;
        int m = m0 + am;
        int s = m >> 9, b = m & 511;
        const float* aptr = data + (size_t)b * (TT * NN) + s * NN + ak;
        int kb = tid >> 5;
        int nb = (tid & 31) * 4;
        const float* bptr = Wx + (size_t)kb * HH + h0 + nb;

#define XA(bf, k, c) sA[((bf) * 16 + (k)) * 132 + (c)]
#define XB(bf, k, c) sB[((bf) * 16 + (k)) * 128 + (c)]

        float4 pa0 = *(const float4*)(aptr);
        float4 pa1 = *(const float4*)(aptr + 4);
        float4 pb0 = *(const float4*)(bptr);
        float4 pb1 = *(const float4*)(bptr + 8 * HH);
        {
            float av[8] = {pa0.x, pa0.y, pa0.z, pa0.w, pa1.x, pa1.y, pa1.z, pa1.w};
#pragma unroll
            for (int jj = 0; jj < 8; ++jj) XA(0, ak + jj, am) = av[jj];
            *(float4*)&XB(0, kb, nb) = pb0;
            *(float4*)&XB(0, kb + 8, nb) = pb1;
        }
        __syncthreads();

        int ty = tid >> 4, tx = tid & 15;
        int mr = ty * 8, nr = tx * 8;
        ull acc[8][4] = {};

#pragma unroll 2
        for (int c = 0; c < 8; ++c) {
            if (c + 1 < 8) {
                int k0 = (c + 1) * 16;
                pa0 = *(const float4*)(aptr + k0);
                pa1 = *(const float4*)(aptr + k0 + 4);
                pb0 = *(const float4*)(bptr + (size_t)k0 * HH);
                pb1 = *(const float4*)(bptr + (size_t)(k0 + 8) * HH);
            }
            int buf = c & 1;
#pragma unroll
            for (int k = 0; k < 16; ++k) {
                float4 a0 = *(const float4*)&XA(buf, k, mr);
                float4 a1 = *(const float4*)&XA(buf, k, mr + 4);
                F4U b0u, b1u;
                b0u.v = *(const float4*)&XB(buf, k, nr);
                b1u.v = *(const float4*)&XB(buf, k, nr + 4);
                float av[8] = {a0.x, a0.y, a0.z, a0.w, a1.x, a1.y, a1.z, a1.w};
                ull bp[4] = {b0u.u[0], b0u.u[1], b1u.u[0], b1u.u[1]};
#pragma unroll
                for (int r = 0; r < 8; ++r) {
                    ull ad = dup2(av[r]);
#pragma unroll
                    for (int p = 0; p < 4; ++p) acc[r][p] = ffma2(ad, bp[p], acc[r][p]);
                }
            }
            if (c + 1 < 8) {
                int nbuf = (c + 1) & 1;
                float av[8] = {pa0.x, pa0.y, pa0.z, pa0.w, pa1.x, pa1.y, pa1.z, pa1.w};
#pragma unroll
                for (int jj = 0; jj < 8; ++jj) XA(nbuf, ak + jj, am) = av[jj];
                *(float4*)&XB(nbuf, kb, nb) = pb0;
                *(float4*)&XB(nbuf, kb + 8, nb) = pb1;
                __syncthreads();
            }
        }

        float bias[8];
#pragma unroll
        for (int cc = 0; cc < 8; ++cc) bias[cc] = __ldg(&bvec[h0 + nr + cc]);
#pragma unroll
        for (int r = 0; r < 8; ++r) {
            float o[8];
            unpk(acc[r][0], o[0], o[1]);
            unpk(acc[r][1], o[2], o[3]);
            unpk(acc[r][2], o[4], o[5]);
            unpk(acc[r][3], o[6], o[7]);
            float* op = g_xW + (size_t)(m0 + mr + r) * HH + h0 + nr;
            float4 o0 = {o[0] + bias[0], o[1] + bias[1], o[2] + bias[2], o[3] + bias[3]};
            float4 o1 = {o[4] + bias[4], o[5] + bias[5], o[6] + bias[6], o[7] + bias[7]};
            *(float4*)&op[0] = o0;
            *(float4*)&op[4] = o1;
        }
#undef XA
#undef XB
    } else {
        // ------------------- pre path -------------------
        float* sA = (float*)smbuf;               // [2][16][128]
        float* sB = (float*)(smbuf + 16384);     // [2][16][128]
        int b = blockIdx.x - 1024;

#define PA(bf, k, c) sA[((bf) * 16 + (k)) * 128 + (c)]
#define PB(bf, k, c) sB[((bf) * 16 + (k)) * 128 + (c)]

        int kb = tid >> 5;
        int nb = (tid & 31) * 4;
        const float* aptr = W1 + (size_t)kb * TT + nb;
        const float* bptr = data + (size_t)b * (TT * NN) + (size_t)kb * NN + nb;

        float4 pa0 = *(const float4*)(aptr);
        float4 pa1 = *(const float4*)(aptr + 8 * TT);
        float4 pb0 = *(const float4*)(bptr);
        float4 pb1 = *(const float4*)(bptr + 8 * NN);
        *(float4*)&PA(0, kb, nb) = pa0;
        *(float4*)&PA(0, kb + 8, nb) = pa1;
        *(float4*)&PB(0, kb, nb) = pb0;
        *(float4*)&PB(0, kb + 8, nb) = pb1;
        __syncthreads();

        int ty = tid >> 4, tx = tid & 15;
        int mr = ty * 8, nr = tx * 8;
        ull acc[8][4] = {};

#pragma unroll 2
        for (int c = 0; c < 8; ++c) {
            if (c + 1 < 8) {
                int k0 = (c + 1) * 16;
                pa0 = *(const float4*)(aptr + (size_t)k0 * TT);
                pa1 = *(const float4*)(aptr + (size_t)(k0 + 8) * TT);
                pb0 = *(const float4*)(bptr + (size_t)k0 * NN);
                pb1 = *(const float4*)(bptr + (size_t)(k0 + 8) * NN);
            }
            int buf = c & 1;
#pragma unroll
            for (int k = 0; k < 16; ++k) {
                float4 a0 = *(const float4*)&PA(buf, k, mr);
                float4 a1 = *(const float4*)&PA(buf, k, mr + 4);
                F4U b0u, b1u;
                b0u.v = *(const float4*)&PB(buf, k, nr);
                b1u.v = *(const float4*)&PB(buf, k, nr + 4);
                float av[8] = {a0.x, a0.y, a0.z, a0.w, a1.x, a1.y, a1.z, a1.w};
                ull bp[4] = {b0u.u[0], b0u.u[1], b1u.u[0], b1u.u[1]};
#pragma unroll
                for (int r = 0; r < 8; ++r) {
                    ull ad = dup2(av[r]);
#pragma unroll
                    for (int p = 0; p < 4; ++p) acc[r][p] = ffma2(ad, bp[p], acc[r][p]);
                }
            }
            if (c + 1 < 8) {
                int nbuf = (c + 1) & 1;
                *(float4*)&PA(nbuf, kb, nb) = pa0;
                *(float4*)&PA(nbuf, kb + 8, nb) = pa1;
                *(float4*)&PB(nbuf, kb, nb) = pb0;
                *(float4*)&PB(nbuf, kb + 8, nb) = pb1;
                __syncthreads();
            }
        }

#pragma unroll
        for (int r = 0; r < 8; ++r) {
            int t = mr + r;
            float bt = __ldg(&b1[t]);
            float o[8];
            unpk(acc[r][0], o[0], o[1]);
            unpk(acc[r][1], o[2], o[3]);
            unpk(acc[r][2], o[4], o[5]);
            unpk(acc[r][3], o[6], o[7]);
            float* op = g_preT + (size_t)b * (TT * NN) + (size_t)t * NN + nr;
            float4 o0 = {o[0] + bt, o[1] + bt, o[2] + bt, o[3] + bt};
            float4 o1 = {o[4] + bt, o[5] + bt, o[6] + bt, o[7] + bt};
            *(float4*)&op[0] = o0;
            *(float4*)&op[4] = o1;
        }
#undef PA
#undef PB
    }
}

// ---------------------------------------------------------------------------
// K_rnn9: best measured RNN (376us, profiled R12). Unchanged.
// ---------------------------------------------------------------------------
__global__ __launch_bounds__(512, 1) void k_rnn9(const float* __restrict__ h0,
                                                 const float* __restrict__ Wh) {
    extern __shared__ float sm[];
    float* sWs = sm;            // [128][256]
    float* sh = sm + 32768;     // [2][256][4]
    float* sred = sh + 2048;    // [256][4]
    int b0 = blockIdx.x * 4;
    int tid = threadIdx.x;
    int j = tid & 255;
    int kh = tid >> 8;

    for (int i = tid; i < 128 * 64; i += 512) {
        int row = i >> 6;
        int c4 = i & 63;
        int gr = (row < 64) ? row : (row + 64);
        ((float4*)sWs)[i] = *(const float4*)&Wh[(size_t)gr * HH + c4 * 4];
    }
    float wr[64];
    {
        const float* wp = Wh + (size_t)(kh * 128 + 64) * HH + j;
#pragma unroll
        for (int c = 0; c < 64; ++c) wr[c] = wp[(size_t)c * HH];
    }
    if (kh == 0) {
        float4 h4;
        h4.x = h0[(size_t)(b0 + 0) * HH + j];
        h4.y = h0[(size_t)(b0 + 1) * HH + j];
        h4.z = h0[(size_t)(b0 + 2) * HH + j];
        h4.w = h0[(size_t)(b0 + 3) * HH + j];
        *(float4*)&sh[j * 4] = h4;
    }
    __syncthreads();

    ull nx01 = 0, nx23 = 0;
    if (kh == 0) {
        const float* xw = g_xW + (size_t)b0 * HH + j;
        nx01 = pack2(xw[0], xw[HH]);
        nx23 = pack2(xw[2 * HH], xw[3 * HH]);
    }

    const float* swj = sWs + j;
    int smbase = kh * 64;
    int hsm = kh * 128;
    int hrg = kh * 128 + 64;

    for (int s = 0; s < TT; ++s) {
        const float* shc = sh + (s & 1) * 1024;
        float* shn = sh + (1 - (s & 1)) * 1024;

        ull a01, a23;
        if (kh == 0) {
            a01 = nx01; a23 = nx23;
            if (s + 1 < TT) {
                const float* xw = g_xW + (size_t)(s + 1) * (BB * HH) + (size_t)b0 * HH + j;
                nx01 = pack2(xw[0], xw[HH]);
                nx23 = pack2(xw[2 * HH], xw[3 * HH]);
            }
        } else {
            a01 = 0; a23 = 0;
        }
        ull c01 = 0, c23 = 0;

#pragma unroll 16
        for (int k = 0; k < 64; ++k) {
            float w = swj[(smbase + k) * 256];
            F4U hu; hu.v = *(const float4*)&shc[(hsm + k) * 4];
            ull wd = dup2(w);
            a01 = ffma2(hu.u[0], wd, a01);
            a23 = ffma2(hu.u[1], wd, a23);
        }
#pragma unroll
        for (int c = 0; c < 64; ++c) {
            ull wd = dup2(wr[c]);
            F4U hu; hu.v = *(const float4*)&shc[(hrg + c) * 4];
            c01 = ffma2(hu.u[0], wd, c01);
            c23 = ffma2(hu.u[1], wd, c23);
        }

        if (kh == 1) {
            F4U r;
            r.u[0] = fadd2(a01, c01);
            r.u[1] = fadd2(a23, c23);
            *(float4*)&sred[j * 4] = r.v;
        }
        __syncthreads();
        if (kh == 0) {
            F4U p; p.v = *(const float4*)&sred[j * 4];
            a01 = fadd2(fadd2(a01, c01), p.u[0]);
            a23 = fadd2(fadd2(a23, c23), p.u[1]);
            float x0, x1, x2, x3;
            unpk(a01, x0, x1);
            unpk(a23, x2, x3);
            float4 h4o = make_float4(tanh_fast(x0), tanh_fast(x1), tanh_fast(x2), tanh_fast(x3));
            *(float4*)&shn[j * 4] = h4o;
            *(float4*)&g_Hs2[((size_t)s * HH + j) * BB + b0] = h4o;
        }
        __syncthreads();
    }
}

// ---------------------------------------------------------------------------
// K_q3: Q[m][t] = Hs-row(m) @ W2 + b2. (unchanged)
// ---------------------------------------------------------------------------
__global__ __launch_bounds__(256, 2) void k_q3(const float* __restrict__ W2,
                                               const float* __restrict__ b2) {
    __shared__ float sA[2][16][132];
    __shared__ float sB[2][16][128];
    int m0 = blockIdx.x * 128;
    int s = m0 >> 9, b0m = m0 & 511;
    int tid = threadIdx.x;

    int kk0 = tid >> 5;
    int mmo = (tid & 31) * 4;
    int kk1 = kk0 + 8;
    const float* aB = g_Hs2 + (size_t)s * HH * BB + b0m + mmo;
    int kb = tid >> 5;
    int nb = (tid & 31) * 4;
    const float* bptr = W2 + (size_t)kb * TT + nb;

    float4 pa0 = *(const float4*)&aB[(size_t)kk0 * BB];
    float4 pa1 = *(const float4*)&aB[(size_t)kk1 * BB];
    float4 pb0 = *(const float4*)(bptr);
    float4 pb1 = *(const float4*)(bptr + 8 * TT);
    *(float4*)&sA[0][kk0][mmo] = pa0;
    *(float4*)&sA[0][kk1][mmo] = pa1;
    *(float4*)&sB[0][kb][nb] = pb0;
    *(float4*)&sB[0][kb + 8][nb] = pb1;
    __syncthreads();

    int ty = tid >> 4, tx = tid & 15;
    int mr = ty * 8, nr = tx * 8;
    ull acc[8][4] = {};

#pragma unroll 2
    for (int c = 0; c < 16; ++c) {
        if (c + 1 < 16) {
            int k0 = (c + 1) * 16;
            pa0 = *(const float4*)&aB[(size_t)(k0 + kk0) * BB];
            pa1 = *(const float4*)&aB[(size_t)(k0 + kk1) * BB];
            pb0 = *(const float4*)(bptr + (size_t)k0 * TT);
            pb1 = *(const float4*)(bptr + (size_t)(k0 + 8) * TT);
        }
        int buf = c & 1;
#pragma unroll
        for (int k = 0; k < 16; ++k) {
            float4 a0 = *(const float4*)&sA[buf][k][mr];
            float4 a1 = *(const float4*)&sA[buf][k][mr + 4];
            F4U b0u, b1u;
            b0u.v = *(const float4*)&sB[buf][k][nr];
            b1u.v = *(const float4*)&sB[buf][k][nr + 4];
            float av[8] = {a0.x, a0.y, a0.z, a0.w, a1.x, a1.y, a1.z, a1.w};
            ull bp[4] = {b0u.u[0], b0u.u[1], b1u.u[0], b1u.u[1]};
#pragma unroll
            for (int r = 0; r < 8; ++r) {
                ull ad = dup2(av[r]);
#pragma unroll
                for (int p = 0; p < 4; ++p) acc[r][p] = ffma2(ad, bp[p], acc[r][p]);
            }
        }
        if (c + 1 < 16) {
            int nbuf = (c + 1) & 1;
            *(float4*)&sA[nbuf][kk0][mmo] = pa0;
            *(float4*)&sA[nbuf][kk1][mmo] = pa1;
            *(float4*)&sB[nbuf][kb][nb] = pb0;
            *(float4*)&sB[nbuf][kb + 8][nb] = pb1;
            __syncthreads();
        }
    }

    float bias[8];
#pragma unroll
    for (int cc = 0; cc < 8; ++cc) bias[cc] = __ldg(&b2[nr + cc]);
#pragma unroll
    for (int r = 0; r < 8; ++r) {
        float o[8];
        unpk(acc[r][0], o[0], o[1]);
        unpk(acc[r][1], o[2], o[3]);
        unpk(acc[r][2], o[4], o[5]);
        unpk(acc[r][3], o[6], o[7]);
        float* op = g_Q + (size_t)(m0 + mr + r) * TT + nr;
        float4 o0 = {o[0] + bias[0], o[1] + bias[1], o[2] + bias[2], o[3] + bias[3]};
        float4 o1 = {o[4] + bias[4], o[5] + bias[5], o[6] + bias[6], o[7] + bias[7]};
        *(float4*)&op[0] = o0;
        *(float4*)&op[4] = o1;
    }
}

// ---------------------------------------------------------------------------
// K_att6: att5 with grid 2048 (quarter-s chunks, 16 iterations/CTA) for
// finer wave granularity. Single barrier/iter, double-buffered sQ/sred,
// q-prefetch, dual e-accumulators.
// ---------------------------------------------------------------------------
__global__ __launch_bounds__(256) void k_att6(const float* __restrict__ data,
                                              const float* __restrict__ Wv,
                                              float* __restrict__ out) {
    extern __shared__ float sm[];
    float* sP = sm;            // [128][128]
    float* sQ = sm + 16384;    // [2][256]
    float* sWv = sQ + 512;     // [128]
    float* sred = sWv + 128;   // [2][8]
    int b = blockIdx.x >> 2;
    int sq = blockIdx.x & 3;
    int tid = threadIdx.x;

    const float4* gP = (const float4*)(g_preT + (size_t)b * (TT * NN));
    for (int i = tid; i < 4096; i += 256) ((float4*)sP)[i] = gP[i];
    if (tid < 128) sWv[tid] = Wv[tid];

    int n = tid & 127;
    int grp = tid >> 7;
    int lane = tid & 31;
    int wig = (tid >> 5) & 3;

    sQ[tid] = g_Q[(size_t)(sq * 32 + grp) * (BB * TT) + b * TT + n];
    __syncthreads();

    for (int si = 0; si < 16; ++si) {
        int cur = si & 1;
        int s = sq * 32 + si * 2 + grp;

        float qn = 0.f;
        if (si + 1 < 16) {
            qn = g_Q[(size_t)(s + 2) * (BB * TT) + b * TT + n];
        }

        const float* qrow = sQ + cur * 256 + grp * 128;
        float e0 = 0.f, e1 = 0.f;
#pragma unroll 4
        for (int t = 0; t < 128; t += 2) {
            e0 += sWv[t] * tanh_fast(sP[t * 128 + n] + qrow[t]);
            e1 += sWv[t + 1] * tanh_fast(sP[(t + 1) * 128 + n] + qrow[t + 1]);
        }
        float e = e0 + e1;

        float ex = __expf(e);
        float sum = ex;
#pragma unroll
        for (int o = 16; o; o >>= 1) sum += __shfl_xor_sync(0xFFFFFFFFu, sum, o);
        if (lane == 0) sred[cur * 8 + grp * 4 + wig] = sum;
        if (si + 1 < 16) sQ[(cur ^ 1) * 256 + tid] = qn;
        __syncthreads();

        const float* sr = sred + cur * 8 + grp * 4;
        sum = sr[0] + sr[1] + sr[2] + sr[3];
        float alpha = ex / sum;

        int bp = 4 * s + (b >> 7);
        int tp = b & 127;
        size_t idx = (size_t)bp * (TT * NN) + tp * NN + n;
        out[idx] = data[idx] * alpha;
    }
}

// ---------------------------------------------------------------------------
extern "C" void kernel_launch(void* const* d_in, const int* in_sizes, int n_in,
                              void* d_out, int out_size) {
    const float* data = (const float*)d_in[0];
    const float* h0 = (const float*)d_in[1];
    const float* Wx = (const float*)d_in[2];
    const float* Wh = (const float*)d_in[3];
    const float* bvec = (const float*)d_in[4];
    const float* W1 = (const float*)d_in[5];
    const float* b1 = (const float*)d_in[6];
    const float* W2 = (const float*)d_in[7];
    const float* b2 = (const float*)d_in[8];
    const float* Wv = (const float*)d_in[9];
    float* out = (float*)d_out;

    const int SM_RNN = (32768 + 2048 + 1024) * 4;    // 140 KB
    const int SM_ATT = (16384 + 512 + 128 + 16) * 4; // ~68 KB

    cudaFuncSetAttribute(k_rnn9, cudaFuncAttributeMaxDynamicSharedMemorySize, SM_RNN);
    cudaFuncSetAttribute(k_att6, cudaFuncAttributeMaxDynamicSharedMemorySize, SM_ATT);

    k_xwpre<<<1536, 256>>>(data, Wx, bvec, W1, b1);
    k_rnn9<<<BB / 4, 512, SM_RNN>>>(h0, Wh);
    k_q3<<<(TT * BB) / 128, 256>>>(W2, b2);
    k_att6<<<BB * 4, 256, SM_ATT>>>(data, Wv, out);
}